// round 13
// baseline (speedup 1.0000x reference)
#include <cuda_runtime.h>
#include <cuda_fp16.h>
#include <cstdint>

// out[b,h] = sum_{d,m} x[b,d,m]*w1[m,h,d]*w2[h,d] + C[h]
//   -> one GEMM: M=256, N=128, K=131072 (k = d*64+m contiguous in x)
//   U[h,k] = w1*w2*256 as single fp16 (err 2^-11); x split exactly fp16 hi+lo
//   out = (xh*U + xl*U)/256 : 2 MMA products.
// Epoch = {cp.async fp32 A + fp16 B} -> bulk convert A to fp16 hi/lo scratch
// (once, not per-warp_n) -> pure ldsm->mma phase.
// mma.sync m16n8k16 f16 (tcgen05 unavailable: harness targets compute_103, no 'a').

static constexpr int Ddim = 2048;
static constexpr int Mhist = 64;
static constexpr int Hdim = 128;
static constexpr int KTOT = Ddim * Mhist;     // 131072
static constexpr int KC = 64;                  // K per chunk
static constexpr int NCHUNK = KTOT / KC;       // 2048
static constexpr int KSPLIT = 74;              // grid.x ; grid.y = 2 -> 148 CTAs
static constexpr float USCALE = 256.0f;
static constexpr float UINV = 1.0f / 256.0f;

__device__ __half g_U[(size_t)Hdim * KTOT];    // 32 MB
__device__ float g_C[Hdim];

__device__ __forceinline__ uint32_t smem_u32(const void* p) {
    uint32_t a;
    asm("{ .reg .u64 t; cvta.to.shared.u64 t, %1; cvt.u32.u64 %0, t; }" : "=r"(a) : "l"(p));
    return a;
}
__device__ __forceinline__ uint32_t sw128(uint32_t off) { return off ^ ((off >> 3) & 0x70); }
// fp32 A tile: 256B rows, XOR-swizzle 32B granules by row%8
__device__ __forceinline__ uint32_t aswz(uint32_t row, uint32_t byte) {
    return row * 256 + (byte ^ ((row & 7) << 5));
}
__device__ __forceinline__ uint32_t h2_bits(__half2 v) {
    return reinterpret_cast<uint32_t&>(v);
}
__device__ __forceinline__ void ldsm_x4(uint32_t& r0, uint32_t& r1, uint32_t& r2, uint32_t& r3,
                                        uint32_t addr) {
    asm volatile("ldmatrix.sync.aligned.m8n8.x4.shared.b16 {%0,%1,%2,%3}, [%4];"
                 : "=r"(r0), "=r"(r1), "=r"(r2), "=r"(r3) : "r"(addr));
}
__device__ __forceinline__ float4 lds128f(uint32_t addr) {
    float4 v;
    asm volatile("ld.shared.v4.f32 {%0,%1,%2,%3}, [%4];"
                 : "=f"(v.x), "=f"(v.y), "=f"(v.z), "=f"(v.w) : "r"(addr));
    return v;
}
__device__ __forceinline__ void sts128(uint32_t addr, uint32_t a, uint32_t b,
                                       uint32_t c, uint32_t d) {
    asm volatile("st.shared.v4.b32 [%0], {%1,%2,%3,%4};"
                 :: "r"(addr), "r"(a), "r"(b), "r"(c), "r"(d));
}
__device__ __forceinline__ void mma16816(float* c, const uint32_t* a, const uint32_t* b) {
    asm volatile(
        "mma.sync.aligned.m16n8k16.row.col.f32.f16.f16.f32 "
        "{%0,%1,%2,%3}, {%4,%5,%6,%7}, {%8,%9}, {%0,%1,%2,%3};"
        : "+f"(c[0]), "+f"(c[1]), "+f"(c[2]), "+f"(c[3])
        : "r"(a[0]), "r"(a[1]), "r"(a[2]), "r"(a[3]), "r"(b[0]), "r"(b[1]));
}
__device__ __forceinline__ void cp_async16(uint32_t dst, const void* src) {
    asm volatile("cp.async.cg.shared.global [%0], [%1], 16;" :: "r"(dst), "l"(src));
}
#define CP_COMMIT() asm volatile("cp.async.commit_group;" ::: "memory")
#define CP_WAIT_2() asm volatile("cp.async.wait_group 2;" ::: "memory")

// ---------------- precompute ----------------
// build_u v3: direct per-thread stores; thread (h,d) reads 64 strided w1 values
// and writes one contiguous 128B line of g_U.
__global__ void build_u_kernel(const float* __restrict__ w1, const float* __restrict__ w2) {
    int g = blockIdx.x * blockDim.x + threadIdx.x;  // 0 .. 128*2048-1
    int h = g >> 11;
    int d = g & 2047;
    float s = w2[h * Ddim + d] * USCALE;
    uint32_t uu[32];
#pragma unroll 16
    for (int m = 0; m < Mhist; m += 2) {
        float a = w1[((size_t)m * Hdim + h) * Ddim + d] * s;
        float b = w1[((size_t)(m + 1) * Hdim + h) * Ddim + d] * s;
        uu[m >> 1] = h2_bits(__floats2half2_rn(a, b));
    }
    uint4* p = reinterpret_cast<uint4*>(g_U + (size_t)h * KTOT + (size_t)d * Mhist);
#pragma unroll
    for (int j = 0; j < 8; j++) p[j] = reinterpret_cast<uint4*>(uu)[j];
}

__global__ void bias_kernel(const float* __restrict__ b1, const float* __restrict__ w2,
                            const float* __restrict__ b2, float* __restrict__ out) {
    __shared__ float red[256];
    int h = blockIdx.x;
    float s = 0.0f;
    for (int d = threadIdx.x; d < Ddim; d += 256)
        s += b1[h * Ddim + d] * w2[h * Ddim + d];
    red[threadIdx.x] = s;
    __syncthreads();
    for (int st = 128; st > 0; st >>= 1) {
        if (threadIdx.x < st) red[threadIdx.x] += red[threadIdx.x + st];
        __syncthreads();
    }
    __syncthreads();
    float C = red[0] + b2[h];
    out[(size_t)threadIdx.x * Hdim + h] = C;
    if (threadIdx.x == 0) g_C[h] = C;
}

// ---------------- GEMM ----------------
// 512 threads = 16 warps (4x4), CTA tile 128x128, warp tile 32x32.
// stage = {A fp32 32K, B fp16 16K} = 48KB; 4 stages. scratch = {AH 16K, AL 16K}.
static constexpr int S_B = 32768;
static constexpr int STAGE = 49152;
static constexpr int NSTAGE = 4;
static constexpr int SCR_AH = NSTAGE * STAGE;            // 196608
static constexpr int SCR_AL = SCR_AH + 16384;            // 212992
static constexpr int SMEM_TOTAL = SCR_AL + 16384;        // 229376

__global__ void __launch_bounds__(512, 1)
gemm_kernel(const float* __restrict__ x, float* __restrict__ out) {
    extern __shared__ char smem[];
    uint32_t sb = smem_u32(smem);
    int tid = threadIdx.x;
    int wid = tid >> 5;
    int lane = tid & 31;
    int warp_m = wid >> 2;
    int warp_n = wid & 3;
    int ksp = blockIdx.x;
    int mtile = blockIdx.y;

    int c0 = (ksp * NCHUNK) / KSPLIT;
    int c1 = ((ksp + 1) * NCHUNK) / KSPLIT;

    // loader/cvt mapping: row = tid>>2 (0..127), q = tid&3 (16-col quarter)
    int arow = tid >> 2;
    int q = tid & 3;
    const float* xr = x + ((size_t)(mtile * 128 + arow)) * KTOT + q * 16;
    const __half* ub = g_U + (size_t)arow * KTOT + q * 16;

    // fp32 A slot offsets (cp.async dst + cvt-phase lds src)
    uint32_t aoA[4];
#pragma unroll
    for (int i = 0; i < 4; i++)
        aoA[i] = aswz((uint32_t)arow, (uint32_t)(q * 64 + i * 16));
    // fp16 SW128 offsets (B cp.async dst + scratch AH/AL sts dst)
    uint32_t boA[2];
    boA[0] = sw128((uint32_t)(arow * 128 + q * 32));
    boA[1] = sw128((uint32_t)(arow * 128 + q * 32 + 16));

    // ldmatrix lane address components (validated R2-R5)
    uint32_t a_row_l = (uint32_t)(warp_m * 32 + (lane & 15));
    uint32_t a_kb_l = (uint32_t)((lane >> 4) * 16);
    uint32_t b_row_l = (uint32_t)(warp_n * 32 + ((lane >> 4) << 3) + (lane & 7));
    uint32_t b_kb_l = (uint32_t)(((lane >> 3) & 1) * 16);

    float acc[2][4][4];
#pragma unroll
    for (int i = 0; i < 2; i++)
#pragma unroll
        for (int j = 0; j < 4; j++)
#pragma unroll
            for (int r = 0; r < 4; r++) acc[i][j][r] = 0.0f;

    // ---- prologue: issue 3 stages ----
#pragma unroll
    for (int pi = 0; pi < 3; pi++) {
        int c = c0 + pi;
        uint32_t st = (uint32_t)pi * STAGE;
        const float* xp = xr + (size_t)c * KC;
        const __half* up = ub + (size_t)c * KC;
#pragma unroll
        for (int i = 0; i < 4; i++) cp_async16(sb + st + aoA[i], xp + i * 4);
        cp_async16(sb + st + S_B + boA[0], up);
        cp_async16(sb + st + S_B + boA[1], up + 8);
        CP_COMMIT();
    }

    for (int c = c0; c < c1; c++) {
        uint32_t stg = (uint32_t)((c - c0) & 3) * STAGE;

        CP_WAIT_2();             // stage(c) landed
        __syncthreads();         // stage(c) visible; prev epoch's scratch readers done

        int cn = c + 3;
        if (cn < c1) {
            uint32_t nst = (uint32_t)((cn - c0) & 3) * STAGE;
            const float* xp = xr + (size_t)cn * KC;
            const __half* up = ub + (size_t)cn * KC;
#pragma unroll
            for (int i = 0; i < 4; i++) cp_async16(sb + nst + aoA[i], xp + i * 4);
            cp_async16(sb + nst + S_B + boA[0], up);
            cp_async16(sb + nst + S_B + boA[1], up + 8);
        }
        CP_COMMIT();

        // ---- conversion phase: fp32 A (stage c) -> fp16 hi/lo scratch, ONCE ----
        {
            uint32_t hw[8], lw[8];
#pragma unroll
            for (int i = 0; i < 4; i++) {
                float4 t = lds128f(sb + stg + aoA[i]);
                __half2 H01 = __floats2half2_rn(t.x, t.y);
                float2 f01 = __half22float2(H01);
                __half2 L01 = __floats2half2_rn(t.x - f01.x, t.y - f01.y);
                __half2 H23 = __floats2half2_rn(t.z, t.w);
                float2 f23 = __half22float2(H23);
                __half2 L23 = __floats2half2_rn(t.z - f23.x, t.w - f23.y);
                hw[2 * i] = h2_bits(H01); hw[2 * i + 1] = h2_bits(H23);
                lw[2 * i] = h2_bits(L01); lw[2 * i + 1] = h2_bits(L23);
            }
            sts128(sb + SCR_AH + boA[0], hw[0], hw[1], hw[2], hw[3]);
            sts128(sb + SCR_AH + boA[1], hw[4], hw[5], hw[6], hw[7]);
            sts128(sb + SCR_AL + boA[0], lw[0], lw[1], lw[2], lw[3]);
            sts128(sb + SCR_AL + boA[1], lw[4], lw[5], lw[6], lw[7]);
        }
        __syncthreads();         // scratch ready

        // ---- MMA phase: pure ldsm -> mma ----
        uint32_t Ah = sb + SCR_AH, Al = sb + SCR_AL, Bb = sb + stg + S_B;
#pragma unroll
        for (int ks = 0; ks < 4; ks++) {
            uint32_t bh[4][2], ah[2][4], al[2][4];
            ldsm_x4(bh[0][0], bh[0][1], bh[1][0], bh[1][1],
                    Bb + sw128(b_row_l * 128 + ks * 32 + b_kb_l));
            ldsm_x4(bh[2][0], bh[2][1], bh[3][0], bh[3][1],
                    Bb + sw128((b_row_l + 16) * 128 + ks * 32 + b_kb_l));
            ldsm_x4(ah[0][0], ah[0][1], ah[0][2], ah[0][3],
                    Ah + sw128(a_row_l * 128 + ks * 32 + a_kb_l));
            ldsm_x4(ah[1][0], ah[1][1], ah[1][2], ah[1][3],
                    Ah + sw128((a_row_l + 16) * 128 + ks * 32 + a_kb_l));
#pragma unroll
            for (int mf = 0; mf < 2; mf++)
#pragma unroll
                for (int nf = 0; nf < 4; nf++)
                    mma16816(acc[mf][nf], ah[mf], bh[nf]);      // xh * U
            ldsm_x4(al[0][0], al[0][1], al[0][2], al[0][3],
                    Al + sw128(a_row_l * 128 + ks * 32 + a_kb_l));
            ldsm_x4(al[1][0], al[1][1], al[1][2], al[1][3],
                    Al + sw128((a_row_l + 16) * 128 + ks * 32 + a_kb_l));
#pragma unroll
            for (int mf = 0; mf < 2; mf++)
#pragma unroll
                for (int nf = 0; nf < 4; nf++)
                    mma16816(acc[mf][nf], al[mf], bh[nf]);      // xl * U
        }
    }

    // ---- epilogue: unscale + split-K atomic reduce (out pre-filled with bias) ----
    int r0 = mtile * 128 + warp_m * 32 + (lane >> 2);
    int cc0 = warp_n * 32 + (lane & 3) * 2;
#pragma unroll
    for (int mf = 0; mf < 2; mf++) {
#pragma unroll
        for (int nf = 0; nf < 4; nf++) {
            int row = r0 + mf * 16;
            int col = cc0 + nf * 8;
            atomicAdd(out + (size_t)row * Hdim + col,           acc[mf][nf][0] * UINV);
            atomicAdd(out + (size_t)row * Hdim + col + 1,       acc[mf][nf][1] * UINV);
            atomicAdd(out + (size_t)(row + 8) * Hdim + col,     acc[mf][nf][2] * UINV);
            atomicAdd(out + (size_t)(row + 8) * Hdim + col + 1, acc[mf][nf][3] * UINV);
        }
    }
}

// ---------------- launch ----------------
extern "C" void kernel_launch(void* const* d_in, const int* in_sizes, int n_in,
                              void* d_out, int out_size) {
    const float* x  = (const float*)d_in[0];
    const float* w1 = (const float*)d_in[1];
    const float* b1 = (const float*)d_in[2];
    const float* w2 = (const float*)d_in[3];
    const float* b2 = (const float*)d_in[4];
    float* out = (float*)d_out;

    cudaFuncSetAttribute(gemm_kernel, cudaFuncAttributeMaxDynamicSharedMemorySize, SMEM_TOTAL);

    build_u_kernel<<<(Hdim * Ddim) / 256, 256>>>(w1, w2);
    bias_kernel<<<Hdim, 256>>>(b1, w2, b2, out);
    dim3 grid(KSPLIT, 2);
    gemm_kernel<<<grid, 512, SMEM_TOTAL>>>(x, out);
}